// round 8
// baseline (speedup 1.0000x reference)
#include <cuda_runtime.h>
#include <cuda_fp16.h>
#include <math.h>

#define FH 50
#define FW 50
#define FC 1024
#define POOL 7

// fp16 staged feature map (5 MB). Static device array => no allocation.
__device__ __half g_fmh[FH * FW * FC];

// fp32->fp16 convert, 2 independent float4 per thread (MLP=2).
// Max is order-preserving under rn-conversion: pooling fp16 then widening
// equals converting the fp32 max (error <= 1 fp16 ulp, ~4.9e-4 rel).
__global__ void __launch_bounds__(256) convert_kernel(const float* __restrict__ fm) {
    const int i = blockIdx.x * 512 + threadIdx.x;
    float4 v0 = reinterpret_cast<const float4*>(fm)[i];
    float4 v1 = reinterpret_cast<const float4*>(fm)[i + 256];
    union { __half2 h[2]; uint2 u; } p0, p1;
    p0.h[0] = __floats2half2_rn(v0.x, v0.y);
    p0.h[1] = __floats2half2_rn(v0.z, v0.w);
    p1.h[0] = __floats2half2_rn(v1.x, v1.y);
    p1.h[1] = __floats2half2_rn(v1.z, v1.w);
    reinterpret_cast<uint2*>(g_fmh)[i] = p0.u;
    reinterpret_cast<uint2*>(g_fmh)[i + 256] = p1.u;
}

// One block per (roi, bin). 128 threads, each owns one uint4 lane (8 halves)
// of the 1024-channel vector. Geometry computed in-block (cheap, redundant
// across the 128 threads but off the critical resource).
__global__ void __launch_bounds__(128) roipool_kernel(
    const float* __restrict__ rois,  // [N,4] (y1,x1,y2,x2) normalized
    float* __restrict__ out)         // [N,7,7,1024] fp32
{
    const int bin = blockIdx.x;      // 0..48
    const int roi = blockIdx.y;
    const int by = bin / POOL;
    const int bx = bin - by * POOL;

    // ROI corners: fp32 multiply then truncating int cast (matches jnp int32 cast for >=0)
    const float4 r = reinterpret_cast<const float4*>(rois)[roi];
    const int h0 = (int)(FH * r.x);
    const int w0 = (int)(FW * r.y);
    const int h1 = (int)(FH * r.z);
    const int w1 = (int)(FW * r.w);
    const int rh = h1 - h0;
    const int rw = w1 - w0;
    const int hstep = rh / POOL;
    const int wstep = rw / POOL;

    // Bin bounds with the reference's empty-bin fixup:
    // grow end by 1 if room, else shrink start by 1.
    int sh = by * hstep;
    int eh = (by < POOL - 1) ? sh + hstep : rh;
    if (sh == eh) { if (eh < rh) eh += 1; else sh -= 1; }
    int sw = bx * wstep;
    int ew = (bx < POOL - 1) ? sw + wstep : rw;
    if (sw == ew) { if (ew < rw) ew += 1; else sw -= 1; }

    const int ys = max(h0 + sh, 0);
    const int ye = h0 + eh;          // <= FH
    const int xs = max(w0 + sw, 0);
    const int xe = w0 + ew;          // <= FW

    const int t = threadIdx.x;       // uint4 lane
    const __half2 ninf = __float2half2_rn(-INFINITY);
    __half2 a0 = ninf, a1 = ninf, a2 = ninf, a3 = ninf;

    // 32-bit indexing: map is 640K uint4, offsets fit easily.
    const int cstride = FC / 8;          // uint4 per cell (128)
    const int rstride = FW * cstride;    // uint4 per feature row
    const uint4* fm4 = reinterpret_cast<const uint4*>(g_fmh);
    const int xspan = xe - xs;

    const uint4* rowp = fm4 + ys * rstride + xs * cstride + t;
    for (int y = ys; y < ye; ++y) {
        const uint4* p = rowp;
        #pragma unroll 2
        for (int k = 0; k < xspan; ++k) {
            union { uint4 u; __half2 h[4]; } v;
            v.u = *p;
            p += cstride;
            a0 = __hmax2(a0, v.h[0]);
            a1 = __hmax2(a1, v.h[1]);
            a2 = __hmax2(a2, v.h[2]);
            a3 = __hmax2(a3, v.h[3]);
        }
        rowp += rstride;
    }

    const int o = (roi * 49 + bin) * (FC / 4) + t * 2;  // float4 units
    float2 f0 = __half22float2(a0), f1 = __half22float2(a1);
    float2 f2 = __half22float2(a2), f3 = __half22float2(a3);
    float4* op = reinterpret_cast<float4*>(out) + o;
    op[0] = make_float4(f0.x, f0.y, f1.x, f1.y);
    op[1] = make_float4(f2.x, f2.y, f3.x, f3.y);
}

extern "C" void kernel_launch(void* const* d_in, const int* in_sizes, int n_in,
                              void* d_out, int out_size) {
    const float* features = (const float*)d_in[0];  // [1,50,50,1024] fp32
    const float* rois     = (const float*)d_in[1];  // [N,4] fp32
    const int nrois = in_sizes[1] / 4;

    // 640K float4 total / 512 per block = 1250 blocks.
    convert_kernel<<<FH * FW * FC / 4 / 512, 256>>>(features);

    dim3 grid(49, nrois);
    roipool_kernel<<<grid, 128>>>(rois, (float*)d_out);
}